// round 16
// baseline (speedup 1.0000x reference)
#include <cuda_runtime.h>
#include <cuda_bf16.h>

#define NN 50000
#define EE 1600000
#define ET (EE + NN)   // edges + self loops
#define IN_CH 128
#define H1C1 32        // 4 heads * 8
#define OUT_CH 64
#define NB 196         // ceil(NN/256) scan blocks
#define FULL 0xFFFFFFFFu

// ---------------- scratch (device globals; no allocation allowed) ----------------
__device__ int   g_deg[NN];              // zero at rest; self-cleaned by scan_final
__device__ int   g_off[NN + 1];
__device__ int   g_pos[NN];
__device__ int   g_csr[ET];              // src indices, grouped by dst
__device__ int   g_bsum[NB];
__device__ __nv_bfloat16 g_h1b[NN * H1C1];    // x @ W1, bf16 payload
__device__ float g_asrc1[NN * 4];
__device__ float g_adst1[NN * 4];
__device__ float g_hr[NN * H1C1];        // relu(norm(agg1)+b1), fp32
__device__ __nv_bfloat16 g_h2b[NN * OUT_CH];  // g_hr @ W2, bf16 payload
__device__ float g_asrc2[NN];
__device__ float g_adst2[NN];

// ================= CSR construction (built once, used by both layers) =============
// histogram real edges; 4 per thread via int4 (dst half contiguous, EE%4==0)
__global__ void hist_kernel(const int* __restrict__ ei) {
    int t = blockIdx.x * blockDim.x + threadIdx.x;
    int base = t * 4;
    if (base >= EE) return;
    int4 d = *reinterpret_cast<const int4*>(&ei[EE + base]);
    atomicAdd(&g_deg[d.x], 1);
    atomicAdd(&g_deg[d.y], 1);
    atomicAdd(&g_deg[d.z], 1);
    atomicAdd(&g_deg[d.w], 1);
}

__global__ void scan_partial() {                 // NB blocks x 256
    __shared__ int sh[256];
    int i = blockIdx.x * 256 + threadIdx.x;
    sh[threadIdx.x] = (i < NN) ? g_deg[i] + 1 : 0;     // +1 = self loop
    __syncthreads();
    for (int o = 128; o; o >>= 1) {
        if (threadIdx.x < o) sh[threadIdx.x] += sh[threadIdx.x + o];
        __syncthreads();
    }
    if (threadIdx.x == 0) g_bsum[blockIdx.x] = sh[0];
}

// per-block exclusive scan; each block reduces bsum[0..bid) itself.
// Plants self-loop at csr[off]; self-cleans g_deg for next graph replay.
__global__ void scan_final() {                   // NB blocks x 256
    __shared__ int sh[256];
    __shared__ int base_sh;
    int t = threadIdx.x;
    int bid = blockIdx.x;
    int bv = (t < bid) ? g_bsum[t] : 0;          // NB<=256
    sh[t] = bv;
    __syncthreads();
    for (int o = 128; o; o >>= 1) {
        if (t < o) sh[t] += sh[t + o];
        __syncthreads();
    }
    if (t == 0) base_sh = sh[0];
    __syncthreads();
    int base = base_sh;
    int i = bid * 256 + t;
    int v = 0;
    if (i < NN) {
        v = g_deg[i] + 1;                        // +1 = self loop
        g_deg[i] = 0;                            // reset for next replay
    }
    sh[t] = v;
    __syncthreads();
    #pragma unroll
    for (int o = 1; o < 256; o <<= 1) {
        int u = (t >= o) ? sh[t - o] : 0;
        __syncthreads();
        sh[t] += u;
        __syncthreads();
    }
    if (i < NN) {
        int off = base + sh[t] - v;              // exclusive prefix
        g_off[i] = off;
        g_pos[i] = off + 1;                      // slot 0 reserved for self loop
        g_csr[off] = i;                          // self loop src
        if (i == NN - 1) g_off[NN] = ET;
    }
}

// scatter real edges; 4 per thread for ATOMG MLP (EE%4==0)
__global__ void fill_kernel(const int* __restrict__ ei) {
    int t = blockIdx.x * blockDim.x + threadIdx.x;
    int base = t * 4;
    if (base >= EE) return;
    int4 s = *reinterpret_cast<const int4*>(&ei[base]);
    int4 d = *reinterpret_cast<const int4*>(&ei[EE + base]);
    int i0 = atomicAdd(&g_pos[d.x], 1);
    int i1 = atomicAdd(&g_pos[d.y], 1);
    int i2 = atomicAdd(&g_pos[d.z], 1);
    int i3 = atomicAdd(&g_pos[d.w], 1);
    g_csr[i0] = s.x;
    g_csr[i1] = s.y;
    g_csr[i2] = s.z;
    g_csr[i3] = s.w;
}

// ---------- layer 1 GEMM + fused attention coefs: h1 = x @ W1 --------------------
__global__ void gemm1_kernel(const float* __restrict__ x, const float* __restrict__ W1,
                             const float* __restrict__ att_src1, const float* __restrict__ att_dst1) {
    __shared__ float Ws[IN_CH * H1C1];   // 16 KB
    __shared__ float xs[8][IN_CH];
    int tid = threadIdx.x;
    for (int i = tid; i < IN_CH * H1C1; i += 256) Ws[i] = W1[i];
    int ty = tid >> 5, lane = tid & 31;
    int row = blockIdx.x * 8 + ty;
    if (row < NN) {
        #pragma unroll
        for (int k = lane; k < IN_CH; k += 32) xs[ty][k] = x[row * IN_CH + k];
    }
    __syncthreads();
    if (row < NN) {
        float acc = 0.f;
        #pragma unroll
        for (int k = 0; k < IN_CH; k++) acc += xs[ty][k] * Ws[k * H1C1 + lane];
        g_h1b[row * H1C1 + lane] = __float2bfloat16(acc);   // bf16 payload
        // fused attention (fp32 exact): 8-lane segment reduction per head
        float ps = acc * __ldg(&att_src1[lane]);   // att_src1 is [4,8] contiguous
        float pd = acc * __ldg(&att_dst1[lane]);
        #pragma unroll
        for (int o = 4; o; o >>= 1) {
            ps += __shfl_xor_sync(FULL, ps, o);
            pd += __shfl_xor_sync(FULL, pd, o);
        }
        if ((lane & 7) == 0) {
            g_asrc1[row * 4 + (lane >> 3)] = ps;
            g_adst1[row * 4 + (lane >> 3)] = pd;
        }
    }
}

// ---------- layer 1 aggregation: warp per dst, 8-way unrolled bf16 gather --------
__global__ void agg1_kernel(const float* __restrict__ b1) {
    int n = (blockIdx.x * blockDim.x + threadIdx.x) >> 5;
    int lane = threadIdx.x & 31;
    if (n >= NN) return;
    int h = lane >> 3;
    float adst = __ldg(&g_adst1[n * 4 + h]);
    int beg = g_off[n], end = g_off[n + 1];
    float acc = 0.f, s = 0.f;
    int k = beg;
    for (; k + 7 < end; k += 8) {
        int s0 = __ldg(&g_csr[k]);
        int s1 = __ldg(&g_csr[k + 1]);
        int s2 = __ldg(&g_csr[k + 2]);
        int s3 = __ldg(&g_csr[k + 3]);
        int s4 = __ldg(&g_csr[k + 4]);
        int s5 = __ldg(&g_csr[k + 5]);
        int s6 = __ldg(&g_csr[k + 6]);
        int s7 = __ldg(&g_csr[k + 7]);
        float l0 = __ldg(&g_asrc1[s0 * 4 + h]) + adst;
        float l1 = __ldg(&g_asrc1[s1 * 4 + h]) + adst;
        float l2 = __ldg(&g_asrc1[s2 * 4 + h]) + adst;
        float l3 = __ldg(&g_asrc1[s3 * 4 + h]) + adst;
        float l4 = __ldg(&g_asrc1[s4 * 4 + h]) + adst;
        float l5 = __ldg(&g_asrc1[s5 * 4 + h]) + adst;
        float l6 = __ldg(&g_asrc1[s6 * 4 + h]) + adst;
        float l7 = __ldg(&g_asrc1[s7 * 4 + h]) + adst;
        float v0 = __bfloat162float(g_h1b[s0 * H1C1 + lane]);
        float v1 = __bfloat162float(g_h1b[s1 * H1C1 + lane]);
        float v2 = __bfloat162float(g_h1b[s2 * H1C1 + lane]);
        float v3 = __bfloat162float(g_h1b[s3 * H1C1 + lane]);
        float v4 = __bfloat162float(g_h1b[s4 * H1C1 + lane]);
        float v5 = __bfloat162float(g_h1b[s5 * H1C1 + lane]);
        float v6 = __bfloat162float(g_h1b[s6 * H1C1 + lane]);
        float v7 = __bfloat162float(g_h1b[s7 * H1C1 + lane]);
        l0 = l0 > 0.f ? l0 : 0.2f * l0;
        l1 = l1 > 0.f ? l1 : 0.2f * l1;
        l2 = l2 > 0.f ? l2 : 0.2f * l2;
        l3 = l3 > 0.f ? l3 : 0.2f * l3;
        l4 = l4 > 0.f ? l4 : 0.2f * l4;
        l5 = l5 > 0.f ? l5 : 0.2f * l5;
        l6 = l6 > 0.f ? l6 : 0.2f * l6;
        l7 = l7 > 0.f ? l7 : 0.2f * l7;
        float w0 = __expf(l0);
        float w1 = __expf(l1);
        float w2 = __expf(l2);
        float w3 = __expf(l3);
        float w4 = __expf(l4);
        float w5 = __expf(l5);
        float w6 = __expf(l6);
        float w7 = __expf(l7);
        acc += w0 * v0 + w1 * v1 + w2 * v2 + w3 * v3;
        acc += w4 * v4 + w5 * v5 + w6 * v6 + w7 * v7;
        s += (w0 + w1) + (w2 + w3) + (w4 + w5) + (w6 + w7);
    }
    for (; k < end; k++) {
        int s0 = __ldg(&g_csr[k]);
        float l0 = __ldg(&g_asrc1[s0 * 4 + h]) + adst;
        l0 = l0 > 0.f ? l0 : 0.2f * l0;
        float w0 = __expf(l0);
        acc += w0 * __bfloat162float(g_h1b[s0 * H1C1 + lane]);
        s += w0;
    }
    g_hr[n * H1C1 + lane] = fmaxf(acc / (s + 1e-16f) + b1[lane], 0.f);
}

// ---------- layer 2 GEMM + fused attention coefs: h2 = g_hr @ W2 -----------------
__global__ void gemm2_kernel(const float* __restrict__ W2,
                             const float* __restrict__ att_src2, const float* __restrict__ att_dst2) {
    __shared__ float Ws[H1C1 * OUT_CH];  // 8 KB
    __shared__ float xs[4][H1C1];
    __shared__ float red[4][2][2];       // [row][src/dst][half]
    int tid = threadIdx.x;
    for (int i = tid; i < H1C1 * OUT_CH; i += 256) Ws[i] = W2[i];
    int ty = tid >> 6, col = tid & 63;
    int row = blockIdx.x * 4 + ty;
    if (row < NN && col < H1C1) xs[ty][col] = g_hr[row * H1C1 + col];
    __syncthreads();
    if (row < NN) {
        float acc = 0.f;
        #pragma unroll
        for (int k = 0; k < H1C1; k++) acc += xs[ty][k] * Ws[k * OUT_CH + col];
        g_h2b[row * OUT_CH + col] = __float2bfloat16(acc);   // bf16 payload
        float ps = acc * __ldg(&att_src2[col]);
        float pd = acc * __ldg(&att_dst2[col]);
        #pragma unroll
        for (int o = 16; o; o >>= 1) {
            ps += __shfl_xor_sync(FULL, ps, o);
            pd += __shfl_xor_sync(FULL, pd, o);
        }
        if ((col & 31) == 0) {
            red[ty][0][col >> 5] = ps;
            red[ty][1][col >> 5] = pd;
        }
    }
    __syncthreads();
    if (row < NN && col == 0) {
        g_asrc2[row] = red[ty][0][0] + red[ty][0][1];
        g_adst2[row] = red[ty][1][0] + red[ty][1][1];
    }
}

// ---------- layer 2 aggregation: warp per dst, bf16x2 gather ---------------------
// lane owns channels (2*lane, 2*lane+1): one bfloat162 load, one float2 store
__global__ void agg2_kernel(float* __restrict__ out, const float* __restrict__ b2) {
    int n = (blockIdx.x * blockDim.x + threadIdx.x) >> 5;
    int lane = threadIdx.x & 31;
    if (n >= NN) return;
    const __nv_bfloat162* h2v = reinterpret_cast<const __nv_bfloat162*>(g_h2b); // [NN*32]
    float adst = __ldg(&g_adst2[n]);
    int beg = g_off[n], end = g_off[n + 1];
    float ax = 0.f, ay = 0.f, s = 0.f;
    int k = beg;
    for (; k + 7 < end; k += 8) {
        int s0 = __ldg(&g_csr[k]);
        int s1 = __ldg(&g_csr[k + 1]);
        int s2 = __ldg(&g_csr[k + 2]);
        int s3 = __ldg(&g_csr[k + 3]);
        int s4 = __ldg(&g_csr[k + 4]);
        int s5 = __ldg(&g_csr[k + 5]);
        int s6 = __ldg(&g_csr[k + 6]);
        int s7 = __ldg(&g_csr[k + 7]);
        float l0 = __ldg(&g_asrc2[s0]) + adst;
        float l1 = __ldg(&g_asrc2[s1]) + adst;
        float l2 = __ldg(&g_asrc2[s2]) + adst;
        float l3 = __ldg(&g_asrc2[s3]) + adst;
        float l4 = __ldg(&g_asrc2[s4]) + adst;
        float l5 = __ldg(&g_asrc2[s5]) + adst;
        float l6 = __ldg(&g_asrc2[s6]) + adst;
        float l7 = __ldg(&g_asrc2[s7]) + adst;
        float2 v0 = __bfloat1622float2(h2v[s0 * 32 + lane]);
        float2 v1 = __bfloat1622float2(h2v[s1 * 32 + lane]);
        float2 v2 = __bfloat1622float2(h2v[s2 * 32 + lane]);
        float2 v3 = __bfloat1622float2(h2v[s3 * 32 + lane]);
        float2 v4 = __bfloat1622float2(h2v[s4 * 32 + lane]);
        float2 v5 = __bfloat1622float2(h2v[s5 * 32 + lane]);
        float2 v6 = __bfloat1622float2(h2v[s6 * 32 + lane]);
        float2 v7 = __bfloat1622float2(h2v[s7 * 32 + lane]);
        l0 = l0 > 0.f ? l0 : 0.2f * l0;
        l1 = l1 > 0.f ? l1 : 0.2f * l1;
        l2 = l2 > 0.f ? l2 : 0.2f * l2;
        l3 = l3 > 0.f ? l3 : 0.2f * l3;
        l4 = l4 > 0.f ? l4 : 0.2f * l4;
        l5 = l5 > 0.f ? l5 : 0.2f * l5;
        l6 = l6 > 0.f ? l6 : 0.2f * l6;
        l7 = l7 > 0.f ? l7 : 0.2f * l7;
        float w0 = __expf(l0);
        float w1 = __expf(l1);
        float w2 = __expf(l2);
        float w3 = __expf(l3);
        float w4 = __expf(l4);
        float w5 = __expf(l5);
        float w6 = __expf(l6);
        float w7 = __expf(l7);
        ax += w0 * v0.x + w1 * v1.x + w2 * v2.x + w3 * v3.x;
        ax += w4 * v4.x + w5 * v5.x + w6 * v6.x + w7 * v7.x;
        ay += w0 * v0.y + w1 * v1.y + w2 * v2.y + w3 * v3.y;
        ay += w4 * v4.y + w5 * v5.y + w6 * v6.y + w7 * v7.y;
        s += (w0 + w1) + (w2 + w3) + (w4 + w5) + (w6 + w7);
    }
    for (; k < end; k++) {
        int s0 = __ldg(&g_csr[k]);
        float l0 = __ldg(&g_asrc2[s0]) + adst;
        l0 = l0 > 0.f ? l0 : 0.2f * l0;
        float w0 = __expf(l0);
        float2 v0 = __bfloat1622float2(h2v[s0 * 32 + lane]);
        ax += w0 * v0.x;
        ay += w0 * v0.y;
        s += w0;
    }
    float inv = 1.f / (s + 1e-16f);
    float2 bb = __ldg(&reinterpret_cast<const float2*>(b2)[lane]);   // channels 2l,2l+1
    float2 r;
    r.x = ax * inv + bb.x;
    r.y = ay * inv + bb.y;
    reinterpret_cast<float2*>(out)[n * 32 + lane] = r;               // channels 2l,2l+1
}

extern "C" void kernel_launch(void* const* d_in, const int* in_sizes, int n_in,
                              void* d_out, int out_size) {
    const float* x        = (const float*)d_in[0];
    const int*   ei       = (const int*)d_in[1];      // int32 (JAX x64 disabled)
    const float* W1       = (const float*)d_in[2];
    const float* att_src1 = (const float*)d_in[3];
    const float* att_dst1 = (const float*)d_in[4];
    const float* b1       = (const float*)d_in[5];
    const float* W2       = (const float*)d_in[6];
    const float* att_src2 = (const float*)d_in[7];
    const float* att_dst2 = (const float*)d_in[8];
    const float* b2       = (const float*)d_in[9];
    float* out = (float*)d_out;

    // ---- CSR build (once, reused by both layers) ----
    hist_kernel<<<(EE / 4 + 255) / 256, 256>>>(ei);
    scan_partial<<<NB, 256>>>();
    scan_final<<<NB, 256>>>();
    fill_kernel<<<(EE / 4 + 255) / 256, 256>>>(ei);

    // ---- layer 1 ----
    gemm1_kernel<<<(NN + 7) / 8, 256>>>(x, W1, att_src1, att_dst1);
    agg1_kernel<<<(NN * 32 + 255) / 256, 256>>>(b1);

    // ---- layer 2 ----
    gemm2_kernel<<<(NN + 3) / 4, 256>>>(W2, att_src2, att_dst2);
    agg2_kernel<<<(NN * 32 + 255) / 256, 256>>>(out, b2);
}

// round 17
// speedup vs baseline: 1.0307x; 1.0307x over previous
#include <cuda_runtime.h>
#include <cuda_bf16.h>

#define NN 50000
#define EE 1600000
#define ET (EE + NN)   // edges + self loops
#define IN_CH 128
#define H1C1 32        // 4 heads * 8
#define OUT_CH 64
#define NB 196         // ceil(NN/256) scan blocks
#define FULL 0xFFFFFFFFu

// ---------------- scratch (device globals; no allocation allowed) ----------------
__device__ int   g_deg[NN];              // zero at rest; self-cleaned by scan_final
__device__ int   g_off[NN + 1];
__device__ int   g_pos[NN];
__device__ int   g_csr[ET];              // src indices, grouped by dst
__device__ int   g_bsum[NB];
__device__ float g_h1[NN * H1C1];        // x @ W1            [N,4,8] fp32
__device__ float g_asrc1[NN * 4];
__device__ float g_adst1[NN * 4];
__device__ float g_hr[NN * H1C1];        // relu(norm(agg1)+b1)
__device__ float g_h2[NN * OUT_CH];      // g_hr @ W2
__device__ float g_asrc2[NN];
__device__ float g_adst2[NN];

// ================= CSR construction (built once, used by both layers) =============
// histogram real edges; 8 per thread via 2x int4 (dst half contiguous, EE%8==0)
__global__ void hist_kernel(const int* __restrict__ ei) {
    int t = blockIdx.x * blockDim.x + threadIdx.x;
    int base = t * 8;
    if (base >= EE) return;
    int4 a = *reinterpret_cast<const int4*>(&ei[EE + base]);
    int4 b = *reinterpret_cast<const int4*>(&ei[EE + base + 4]);
    atomicAdd(&g_deg[a.x], 1);
    atomicAdd(&g_deg[a.y], 1);
    atomicAdd(&g_deg[a.z], 1);
    atomicAdd(&g_deg[a.w], 1);
    atomicAdd(&g_deg[b.x], 1);
    atomicAdd(&g_deg[b.y], 1);
    atomicAdd(&g_deg[b.z], 1);
    atomicAdd(&g_deg[b.w], 1);
}

__global__ void scan_partial() {                 // NB blocks x 256
    __shared__ int sh[256];
    int i = blockIdx.x * 256 + threadIdx.x;
    sh[threadIdx.x] = (i < NN) ? g_deg[i] + 1 : 0;     // +1 = self loop
    __syncthreads();
    for (int o = 128; o; o >>= 1) {
        if (threadIdx.x < o) sh[threadIdx.x] += sh[threadIdx.x + o];
        __syncthreads();
    }
    if (threadIdx.x == 0) g_bsum[blockIdx.x] = sh[0];
}

// per-block exclusive scan; each block reduces bsum[0..bid) itself.
// Plants self-loop at csr[off]; self-cleans g_deg for graph replay determinism.
__global__ void scan_final() {                   // NB blocks x 256
    __shared__ int sh[256];
    __shared__ int base_sh;
    int t = threadIdx.x;
    int bid = blockIdx.x;
    int bv = (t < bid) ? g_bsum[t] : 0;          // NB<=256
    sh[t] = bv;
    __syncthreads();
    for (int o = 128; o; o >>= 1) {
        if (t < o) sh[t] += sh[t + o];
        __syncthreads();
    }
    if (t == 0) base_sh = sh[0];
    __syncthreads();
    int base = base_sh;
    int i = bid * 256 + t;
    int v = 0;
    if (i < NN) {
        v = g_deg[i] + 1;                        // +1 = self loop
        g_deg[i] = 0;                            // reset for next replay
    }
    sh[t] = v;
    __syncthreads();
    #pragma unroll
    for (int o = 1; o < 256; o <<= 1) {
        int u = (t >= o) ? sh[t - o] : 0;
        __syncthreads();
        sh[t] += u;
        __syncthreads();
    }
    if (i < NN) {
        int off = base + sh[t] - v;              // exclusive prefix
        g_off[i] = off;
        g_pos[i] = off + 1;                      // slot 0 reserved for self loop
        g_csr[off] = i;                          // self loop src
        if (i == NN - 1) g_off[NN] = ET;
    }
}

// scatter real edges; 8 per thread for ATOMG MLP (EE%8==0)
__global__ void fill_kernel(const int* __restrict__ ei) {
    int t = blockIdx.x * blockDim.x + threadIdx.x;
    int base = t * 8;
    if (base >= EE) return;
    int4 sa = *reinterpret_cast<const int4*>(&ei[base]);
    int4 sb = *reinterpret_cast<const int4*>(&ei[base + 4]);
    int4 da = *reinterpret_cast<const int4*>(&ei[EE + base]);
    int4 db = *reinterpret_cast<const int4*>(&ei[EE + base + 4]);
    int i0 = atomicAdd(&g_pos[da.x], 1);
    int i1 = atomicAdd(&g_pos[da.y], 1);
    int i2 = atomicAdd(&g_pos[da.z], 1);
    int i3 = atomicAdd(&g_pos[da.w], 1);
    int i4 = atomicAdd(&g_pos[db.x], 1);
    int i5 = atomicAdd(&g_pos[db.y], 1);
    int i6 = atomicAdd(&g_pos[db.z], 1);
    int i7 = atomicAdd(&g_pos[db.w], 1);
    g_csr[i0] = sa.x;
    g_csr[i1] = sa.y;
    g_csr[i2] = sa.z;
    g_csr[i3] = sa.w;
    g_csr[i4] = sb.x;
    g_csr[i5] = sb.y;
    g_csr[i6] = sb.z;
    g_csr[i7] = sb.w;
}

// ---------- layer 1 GEMM + fused attention coefs: h1 = x @ W1 --------------------
__global__ void gemm1_kernel(const float* __restrict__ x, const float* __restrict__ W1,
                             const float* __restrict__ att_src1, const float* __restrict__ att_dst1) {
    __shared__ float Ws[IN_CH * H1C1];   // 16 KB
    __shared__ float xs[8][IN_CH];
    int tid = threadIdx.x;
    for (int i = tid; i < IN_CH * H1C1; i += 256) Ws[i] = W1[i];
    int ty = tid >> 5, lane = tid & 31;
    int row = blockIdx.x * 8 + ty;
    if (row < NN) {
        #pragma unroll
        for (int k = lane; k < IN_CH; k += 32) xs[ty][k] = x[row * IN_CH + k];
    }
    __syncthreads();
    if (row < NN) {
        float acc = 0.f;
        #pragma unroll
        for (int k = 0; k < IN_CH; k++) acc += xs[ty][k] * Ws[k * H1C1 + lane];
        g_h1[row * H1C1 + lane] = acc;
        // fused attention (fp32 exact): 8-lane segment reduction per head
        float ps = acc * __ldg(&att_src1[lane]);   // att_src1 is [4,8] contiguous
        float pd = acc * __ldg(&att_dst1[lane]);
        #pragma unroll
        for (int o = 4; o; o >>= 1) {
            ps += __shfl_xor_sync(FULL, ps, o);
            pd += __shfl_xor_sync(FULL, pd, o);
        }
        if ((lane & 7) == 0) {
            g_asrc1[row * 4 + (lane >> 3)] = ps;
            g_adst1[row * 4 + (lane >> 3)] = pd;
        }
    }
}

// ---------- layer 1 aggregation: 2 nodes per warp, float2 channels ---------------
// half-warp per node; lane's pair index c covers channels (2c, 2c+1), head = c>>2.
// Inactive edges use clamped index + w=0 (loads stay unpredicated & batched).
__global__ void agg1_kernel(const float* __restrict__ b1) {
    int gw = (blockIdx.x * blockDim.x + threadIdx.x) >> 5;
    int lane = threadIdx.x & 31;
    int n = gw * 2 + (lane >> 4);            // grid sized so n < NN always
    int c = lane & 15;
    int h = c >> 2;
    const float2* h1v = reinterpret_cast<const float2*>(g_h1);   // [NN*16]
    float adst = __ldg(&g_adst1[n * 4 + h]);
    int beg = g_off[n];
    int len = g_off[n + 1] - beg;            // >= 1 (self loop)
    int mlen = max(len, __shfl_xor_sync(FULL, len, 16));
    float ax = 0.f, ay = 0.f, s = 0.f;
    for (int i = 0; i < mlen; i += 4) {
        int j0 = beg + min(i,     len - 1);
        int j1 = beg + min(i + 1, len - 1);
        int j2 = beg + min(i + 2, len - 1);
        int j3 = beg + min(i + 3, len - 1);
        int s0 = __ldg(&g_csr[j0]);
        int s1 = __ldg(&g_csr[j1]);
        int s2 = __ldg(&g_csr[j2]);
        int s3 = __ldg(&g_csr[j3]);
        float l0 = __ldg(&g_asrc1[s0 * 4 + h]) + adst;
        float l1 = __ldg(&g_asrc1[s1 * 4 + h]) + adst;
        float l2 = __ldg(&g_asrc1[s2 * 4 + h]) + adst;
        float l3 = __ldg(&g_asrc1[s3 * 4 + h]) + adst;
        float2 v0 = __ldg(&h1v[s0 * 16 + c]);
        float2 v1 = __ldg(&h1v[s1 * 16 + c]);
        float2 v2 = __ldg(&h1v[s2 * 16 + c]);
        float2 v3 = __ldg(&h1v[s3 * 16 + c]);
        l0 = l0 > 0.f ? l0 : 0.2f * l0;
        l1 = l1 > 0.f ? l1 : 0.2f * l1;
        l2 = l2 > 0.f ? l2 : 0.2f * l2;
        l3 = l3 > 0.f ? l3 : 0.2f * l3;
        float w0 = (i     < len) ? __expf(l0) : 0.f;
        float w1 = (i + 1 < len) ? __expf(l1) : 0.f;
        float w2 = (i + 2 < len) ? __expf(l2) : 0.f;
        float w3 = (i + 3 < len) ? __expf(l3) : 0.f;
        ax += w0 * v0.x + w1 * v1.x + w2 * v2.x + w3 * v3.x;
        ay += w0 * v0.y + w1 * v1.y + w2 * v2.y + w3 * v3.y;
        s += (w0 + w1) + (w2 + w3);
    }
    float inv = 1.f / (s + 1e-16f);
    float2 bb = __ldg(&reinterpret_cast<const float2*>(b1)[c]);
    float2 r;
    r.x = fmaxf(ax * inv + bb.x, 0.f);
    r.y = fmaxf(ay * inv + bb.y, 0.f);
    reinterpret_cast<float2*>(g_hr)[n * 16 + c] = r;
}

// ---------- layer 2 GEMM + fused attention coefs: h2 = g_hr @ W2 -----------------
__global__ void gemm2_kernel(const float* __restrict__ W2,
                             const float* __restrict__ att_src2, const float* __restrict__ att_dst2) {
    __shared__ float Ws[H1C1 * OUT_CH];  // 8 KB
    __shared__ float xs[4][H1C1];
    __shared__ float red[4][2][2];       // [row][src/dst][half]
    int tid = threadIdx.x;
    for (int i = tid; i < H1C1 * OUT_CH; i += 256) Ws[i] = W2[i];
    int ty = tid >> 6, col = tid & 63;
    int row = blockIdx.x * 4 + ty;
    if (row < NN && col < H1C1) xs[ty][col] = g_hr[row * H1C1 + col];
    __syncthreads();
    if (row < NN) {
        float acc = 0.f;
        #pragma unroll
        for (int k = 0; k < H1C1; k++) acc += xs[ty][k] * Ws[k * OUT_CH + col];
        g_h2[row * OUT_CH + col] = acc;
        float ps = acc * __ldg(&att_src2[col]);
        float pd = acc * __ldg(&att_dst2[col]);
        #pragma unroll
        for (int o = 16; o; o >>= 1) {
            ps += __shfl_xor_sync(FULL, ps, o);
            pd += __shfl_xor_sync(FULL, pd, o);
        }
        if ((col & 31) == 0) {
            red[ty][0][col >> 5] = ps;
            red[ty][1][col >> 5] = pd;
        }
    }
    __syncthreads();
    if (row < NN && col == 0) {
        g_asrc2[row] = red[ty][0][0] + red[ty][0][1];
        g_adst2[row] = red[ty][1][0] + red[ty][1][1];
    }
}

// ---------- layer 2 aggregation: 2 nodes per warp, float4 channels ---------------
// half-warp per node; lane's quad index c covers channels 4c..4c+3.
__global__ void agg2_kernel(float* __restrict__ out, const float* __restrict__ b2) {
    int gw = (blockIdx.x * blockDim.x + threadIdx.x) >> 5;
    int lane = threadIdx.x & 31;
    int n = gw * 2 + (lane >> 4);            // grid sized so n < NN always
    int c = lane & 15;
    const float4* h2v = reinterpret_cast<const float4*>(g_h2);   // [NN*16]
    float adst = __ldg(&g_adst2[n]);
    int beg = g_off[n];
    int len = g_off[n + 1] - beg;            // >= 1
    int mlen = max(len, __shfl_xor_sync(FULL, len, 16));
    float a0 = 0.f, a1 = 0.f, a2 = 0.f, a3 = 0.f, s = 0.f;
    for (int i = 0; i < mlen; i += 4) {
        int j0 = beg + min(i,     len - 1);
        int j1 = beg + min(i + 1, len - 1);
        int j2 = beg + min(i + 2, len - 1);
        int j3 = beg + min(i + 3, len - 1);
        int s0 = __ldg(&g_csr[j0]);
        int s1 = __ldg(&g_csr[j1]);
        int s2 = __ldg(&g_csr[j2]);
        int s3 = __ldg(&g_csr[j3]);
        float l0 = __ldg(&g_asrc2[s0]) + adst;
        float l1 = __ldg(&g_asrc2[s1]) + adst;
        float l2 = __ldg(&g_asrc2[s2]) + adst;
        float l3 = __ldg(&g_asrc2[s3]) + adst;
        float4 v0 = __ldg(&h2v[s0 * 16 + c]);
        float4 v1 = __ldg(&h2v[s1 * 16 + c]);
        float4 v2 = __ldg(&h2v[s2 * 16 + c]);
        float4 v3 = __ldg(&h2v[s3 * 16 + c]);
        l0 = l0 > 0.f ? l0 : 0.2f * l0;
        l1 = l1 > 0.f ? l1 : 0.2f * l1;
        l2 = l2 > 0.f ? l2 : 0.2f * l2;
        l3 = l3 > 0.f ? l3 : 0.2f * l3;
        float w0 = (i     < len) ? __expf(l0) : 0.f;
        float w1 = (i + 1 < len) ? __expf(l1) : 0.f;
        float w2 = (i + 2 < len) ? __expf(l2) : 0.f;
        float w3 = (i + 3 < len) ? __expf(l3) : 0.f;
        a0 += w0 * v0.x + w1 * v1.x + w2 * v2.x + w3 * v3.x;
        a1 += w0 * v0.y + w1 * v1.y + w2 * v2.y + w3 * v3.y;
        a2 += w0 * v0.z + w1 * v1.z + w2 * v2.z + w3 * v3.z;
        a3 += w0 * v0.w + w1 * v1.w + w2 * v2.w + w3 * v3.w;
        s += (w0 + w1) + (w2 + w3);
    }
    float inv = 1.f / (s + 1e-16f);
    float4 bb = __ldg(&reinterpret_cast<const float4*>(b2)[c]);
    float4 r;
    r.x = a0 * inv + bb.x;
    r.y = a1 * inv + bb.y;
    r.z = a2 * inv + bb.z;
    r.w = a3 * inv + bb.w;
    reinterpret_cast<float4*>(out)[n * 16 + c] = r;
}

extern "C" void kernel_launch(void* const* d_in, const int* in_sizes, int n_in,
                              void* d_out, int out_size) {
    const float* x        = (const float*)d_in[0];
    const int*   ei       = (const int*)d_in[1];      // int32 (JAX x64 disabled)
    const float* W1       = (const float*)d_in[2];
    const float* att_src1 = (const float*)d_in[3];
    const float* att_dst1 = (const float*)d_in[4];
    const float* b1       = (const float*)d_in[5];
    const float* W2       = (const float*)d_in[6];
    const float* att_src2 = (const float*)d_in[7];
    const float* att_dst2 = (const float*)d_in[8];
    const float* b2       = (const float*)d_in[9];
    float* out = (float*)d_out;

    // ---- CSR build (once, reused by both layers) ----
    hist_kernel<<<(EE / 8 + 255) / 256, 256>>>(ei);
    scan_partial<<<NB, 256>>>();
    scan_final<<<NB, 256>>>();
    fill_kernel<<<(EE / 8 + 255) / 256, 256>>>(ei);

    // ---- layer 1 ----
    gemm1_kernel<<<(NN + 7) / 8, 256>>>(x, W1, att_src1, att_dst1);
    agg1_kernel<<<(NN / 2 * 32 + 255) / 256, 256>>>(b1);     // 2 nodes / warp

    // ---- layer 2 ----
    gemm2_kernel<<<(NN + 3) / 4, 256>>>(W2, att_src2, att_dst2);
    agg2_kernel<<<(NN / 2 * 32 + 255) / 256, 256>>>(out, b2); // 2 nodes / warp
}